// round 12
// baseline (speedup 1.0000x reference)
#include <cuda_runtime.h>
#include <cstdint>

#define B_      8
#define V_      50000
#define C_      256
#define PC_     64
#define K_      9
#define KIN1_   (K_ * PC_)          // 576
#define M_TOTAL (B_ * V_)           // 400000
#define TILE_M  128

// ---- SMEM layout (32-bit words) ----
// ph1: offs[1152] | AS1A[128*36] | AS1B[128*36] | BS1A[64*36] | BS1B[64*36] = 14976
// ph2 overlays [0,18432): BS2A[256*36]=9216 | BS2B[256*36]=9216 ; bias2[256] @ 18432
// Af[128*260] at 18688.
#define OFFS_OFF   0
#define AS1A_OFF   1152
#define AS1B_OFF   (AS1A_OFF + 128*36)  // 5760
#define BS1A_OFF   (AS1B_OFF + 128*36)  // 10368
#define BS1B_OFF   (BS1A_OFF + 64*36)   // 12672
#define BS2A_OFF   0
#define BS2B_OFF   9216
#define BIAS2_OFF  18432
#define AF_OFF     18688
#define S1_ST      36                   // 36 % 32 == 4 -> conflict-free
#define AF_ST      260                  // 260 % 32 == 4
#define SMEM_WORDS (AF_OFF + 128*AF_ST) // 51968 words = 207872 bytes
#define NCH1       18                   // phase-1 k-chunks of 32

__device__ __forceinline__ unsigned f2tf(float f) {
    unsigned u = __float_as_uint(f);
    return (u + 0xFFFu + ((u >> 13) & 1u)) & 0xFFFFE000u;
}
__device__ __forceinline__ uint4 f2tf4(float4 v) {
    return make_uint4(f2tf(v.x), f2tf(v.y), f2tf(v.z), f2tf(v.w));
}

__device__ __forceinline__ void mma8(float* c, const unsigned* a, unsigned u0, unsigned u1) {
    asm volatile(
        "mma.sync.aligned.m16n8k8.row.col.f32.tf32.tf32.f32 "
        "{%0,%1,%2,%3}, {%4,%5,%6,%7}, {%8,%9}, {%0,%1,%2,%3};"
        : "+f"(c[0]), "+f"(c[1]), "+f"(c[2]), "+f"(c[3])
        : "r"(a[0]), "r"(a[1]), "r"(a[2]), "r"(a[3]), "r"(u0), "r"(u1));
}

__global__ void __launch_bounds__(256, 1)
fused_spiral(const float* x,
             const int* idx,            // int32 (JAX x64 disabled)
             const float* W1,
             const float* b1,
             const float* W2,
             const float* b2,
             float* out)
{
    extern __shared__ unsigned sm[];
    int*      offs  = (int*)(sm + OFFS_OFF);
    float*    bias2 = (float*)(sm + BIAS2_OFF);
    unsigned* Af    = sm + AF_OFF;

    const int tid = threadIdx.x;
    const int m0  = blockIdx.x * TILE_M;
    const int warp = tid >> 5, lane = tid & 31;
    const int wm = warp & 3;                 // ph1 m group: wm*32
    const int wn = warp >> 2;                // ph1 n group: wn*32
    const int lg = lane >> 2, lq = lane & 3;

    // ---- Gather row offsets; defensive clamp ----
    for (int i = tid; i < TILE_M * K_; i += 256) {
        int r = i / K_;
        int k = i - r * K_;
        int m = m0 + r;
        int b = m / V_;
        int v = m - b * V_;
        int id = idx[v * K_ + k];
        id = id < 0 ? 0 : (id >= V_ ? V_ - 1 : id);
        offs[i] = (b * V_ + id) * C_;
    }
    __syncthreads();   // offs visible to all loaders

    // ---- Preload x untouched cols [64,256) into Af (tf32) ----
    for (int q = tid; q < 128 * 48; q += 256) {
        int row = q / 48;
        int c4  = q - row * 48;
        float4 v4 = *(const float4*)(x + (size_t)(m0 + row) * C_ + PC_ + c4 * 4);
        *(uint4*)(Af + row * AF_ST + PC_ + c4 * 4) = f2tf4(v4);
    }

    // ================= Phase 1: gather + GEMM1 (128x64, K=576), k-chunks of 32 =================
    float acc1[2][4][4];
    #pragma unroll
    for (int i = 0; i < 2; i++)
        #pragma unroll
        for (int j = 0; j < 4; j++)
            #pragma unroll
            for (int l = 0; l < 4; l++) acc1[i][j][l] = 0.f;

    const int arow = tid >> 1, ah = tid & 1;     // A loader: row, 16-float half of 32
    const int brow = tid >> 2, bq = tid & 3;     // B loader: out-row, 8-float quarter

    float4 pa[4], pb[2];
    {   // prologue: chunk 0 (g=0, h=0)
        const float4* sA = (const float4*)(x + offs[arow * K_] + ah * 16);
        #pragma unroll
        for (int j = 0; j < 4; j++) pa[j] = sA[j];
        const float4* sB = (const float4*)(W1 + brow * KIN1_ + bq * 8);
        pb[0] = sB[0]; pb[1] = sB[1];
    }

    for (int kc = 0; kc < NCH1; kc++) {
        unsigned* As = sm + ((kc & 1) ? AS1B_OFF : AS1A_OFF);
        unsigned* Bs = sm + ((kc & 1) ? BS1B_OFF : BS1A_OFF);
        {   // STS prefetched slab (tf32 at store)
            unsigned* dA = As + arow * S1_ST + ah * 16;
            #pragma unroll
            for (int j = 0; j < 4; j++) *(uint4*)(dA + j * 4) = f2tf4(pa[j]);
            unsigned* dB = Bs + brow * S1_ST + bq * 8;
            *(uint4*)(dB)     = f2tf4(pb[0]);
            *(uint4*)(dB + 4) = f2tf4(pb[1]);
        }
        if (kc + 1 < NCH1) {   // prefetch next chunk (lands during mma below)
            int g = (kc + 1) >> 1, h = (kc + 1) & 1;
            const float4* sA = (const float4*)(x + offs[arow * K_ + g] + h * 32 + ah * 16);
            #pragma unroll
            for (int j = 0; j < 4; j++) pa[j] = sA[j];
            const float4* sB = (const float4*)(W1 + brow * KIN1_ + (kc + 1) * 32 + bq * 8);
            pb[0] = sB[0]; pb[1] = sB[1];
        }
        __syncthreads();       // slab ready; also recycles other buffer safely

        #pragma unroll
        for (int kk = 0; kk < 32; kk += 8) {
            unsigned a[2][4];
            #pragma unroll
            for (int ms = 0; ms < 2; ms++) {
                const unsigned* p = As + (wm * 32 + ms * 16 + lg) * S1_ST + kk + lq;
                a[ms][0] = p[0];
                a[ms][1] = p[8 * S1_ST];
                a[ms][2] = p[4];
                a[ms][3] = p[8 * S1_ST + 4];
            }
            #pragma unroll
            for (int ns = 0; ns < 4; ns++) {
                const unsigned* p = Bs + (wn * 32 + ns * 8 + lg) * S1_ST + kk + lq;
                unsigned u0 = p[0], u1 = p[4];
                mma8(acc1[0][ns], a[0], u0, u1);
                mma8(acc1[1][ns], a[1], u0, u1);
            }
        }
    }
    __syncthreads();   // all ph1 mma done before overlay region is rewritten

    // ---- P epilogue: + b1, tf32, into Af cols [0,64) ----
    #pragma unroll
    for (int ms = 0; ms < 2; ms++) {
        #pragma unroll
        for (int ns = 0; ns < 4; ns++) {
            int row = wm * 32 + ms * 16 + lg;
            int col = wn * 32 + ns * 8 + lq * 2;
            float bv0 = b1[col], bv1 = b1[col + 1];
            *(uint2*)(Af + row * AF_ST + col) =
                make_uint2(f2tf(acc1[ms][ns][0] + bv0), f2tf(acc1[ms][ns][1] + bv1));
            *(uint2*)(Af + (row + 8) * AF_ST + col) =
                make_uint2(f2tf(acc1[ms][ns][2] + bv0), f2tf(acc1[ms][ns][3] + bv1));
        }
    }
    bias2[tid] = b2[tid];

    // ================= Phase 2: out = Af(128x256) @ W2^T + b2 =================
    // 8 warps as 2m x 4n; warp tile 64x64; full 128x256 in ONE pass (8 syncs).
    const int wm2 = warp & 1;      // rows wm2*64
    const int wn2 = warp >> 1;     // cols wn2*64
    float acc2[4][8][4];
    #pragma unroll
    for (int i = 0; i < 4; i++)
        #pragma unroll
        for (int j = 0; j < 8; j++)
            #pragma unroll
            for (int l = 0; l < 4; l++) acc2[i][j][l] = 0.f;

    float4 pw[8];
    {   // prologue: W2[tid][0..32)
        const float4* sB = (const float4*)(W2 + (size_t)tid * C_);
        #pragma unroll
        for (int j = 0; j < 8; j++) pw[j] = sB[j];
    }

    for (int kc = 0; kc < 8; kc++) {
        unsigned* Bs = sm + ((kc & 1) ? BS2B_OFF : BS2A_OFF);
        {   // STS prefetched W2 slab: thread owns out-row tid, 32 k-floats
            unsigned* dB = Bs + tid * S1_ST;
            #pragma unroll
            for (int j = 0; j < 8; j++) *(uint4*)(dB + j * 4) = f2tf4(pw[j]);
        }
        if (kc + 1 < 8) {   // prefetch next slab — overlaps mma below
            const float4* sB = (const float4*)(W2 + (size_t)tid * C_ + (kc + 1) * 32);
            #pragma unroll
            for (int j = 0; j < 8; j++) pw[j] = sB[j];
        }
        __syncthreads();   // slab ready; first iter also covers P/bias writes

        #pragma unroll
        for (int kk = 0; kk < 32; kk += 8) {
            unsigned a[4][4];
            #pragma unroll
            for (int ms = 0; ms < 4; ms++) {
                const unsigned* p =
                    Af + (wm2 * 64 + ms * 16 + lg) * AF_ST + kc * 32 + kk + lq;
                a[ms][0] = p[0];
                a[ms][1] = p[8 * AF_ST];
                a[ms][2] = p[4];
                a[ms][3] = p[8 * AF_ST + 4];
            }
            #pragma unroll
            for (int ns = 0; ns < 8; ns++) {
                const unsigned* p = Bs + (wn2 * 64 + ns * 8 + lg) * S1_ST + kk + lq;
                unsigned u0 = p[0], u1 = p[4];
                #pragma unroll
                for (int ms = 0; ms < 4; ms++)
                    mma8(acc2[ms][ns], a[ms], u0, u1);
            }
        }
    }

    // Epilogue: + b2, store out
    #pragma unroll
    for (int ms = 0; ms < 4; ms++) {
        #pragma unroll
        for (int ns = 0; ns < 8; ns++) {
            int row = m0 + wm2 * 64 + ms * 16 + lg;
            int col = wn2 * 64 + ns * 8 + lq * 2;
            float bv0 = bias2[col], bv1 = bias2[col + 1];
            *(float2*)(out + (size_t)row * C_ + col) =
                make_float2(acc2[ms][ns][0] + bv0, acc2[ms][ns][1] + bv1);
            *(float2*)(out + (size_t)(row + 8) * C_ + col) =
                make_float2(acc2[ms][ns][2] + bv0, acc2[ms][ns][3] + bv1);
        }
    }
}

extern "C" void kernel_launch(void* const* d_in, const int* in_sizes, int n_in,
                              void* d_out, int out_size) {
    const float* x   = (const float*)d_in[0];
    const int*   idx = (const int*)d_in[1];
    const float* W1  = (const float*)d_in[2];
    const float* b1  = (const float*)d_in[3];
    const float* W2  = (const float*)d_in[4];
    const float* b2  = (const float*)d_in[5];
    float*       out = (float*)d_out;

    const int smem = SMEM_WORDS * 4;   // 207872 bytes
    cudaFuncSetAttribute(fused_spiral, cudaFuncAttributeMaxDynamicSharedMemorySize, smem);
    fused_spiral<<<M_TOTAL / TILE_M, 256, smem>>>(x, idx, W1, b1, W2, b2, out);
}

// round 13
// speedup vs baseline: 1.2558x; 1.2558x over previous
#include <cuda_runtime.h>
#include <cstdint>

#define B_      8
#define V_      50000
#define C_      256
#define PC_     64
#define K_      9
#define KIN1_   (K_ * PC_)          // 576
#define M_TOTAL (B_ * V_)           // 400000
#define TILE_M  128

// ---- SMEM layout (32-bit words), 2 CTAs/SM ----
// persistent: P[128*68] @ 0                                  (8704)
// ph1: offs[1152] @ 8704 | AS1A/B[128*36] @ 9856/14464 | BS1A/B[64*36] @ 19072/21376
// ph2 overlays [8704,27136): BS2A/B[128*36] @ 8704/13312 | AXA/B[128*36] @ 17920/22528
#define P_OFF      0
#define P_ST       68                   // 68 % 32 == 4 -> conflict-free
#define OFFS_OFF   8704
#define AS1A_OFF   9856
#define AS1B_OFF   14464
#define BS1A_OFF   19072
#define BS1B_OFF   21376
#define BS2A_OFF   8704
#define BS2B_OFF   13312
#define AXA_OFF    17920
#define AXB_OFF    22528
#define S_ST       36                   // 36 % 32 == 4
#define SMEM_WORDS 27136                // 108544 bytes -> 2 CTAs/SM
#define NCH1       18                   // phase-1 k-chunks of 32

__device__ __forceinline__ unsigned f2tf(float f) {
    unsigned u = __float_as_uint(f);
    return (u + 0xFFFu + ((u >> 13) & 1u)) & 0xFFFFE000u;
}
__device__ __forceinline__ uint4 f2tf4(float4 v) {
    return make_uint4(f2tf(v.x), f2tf(v.y), f2tf(v.z), f2tf(v.w));
}

__device__ __forceinline__ void mma8(float* c, const unsigned* a, unsigned u0, unsigned u1) {
    asm volatile(
        "mma.sync.aligned.m16n8k8.row.col.f32.tf32.tf32.f32 "
        "{%0,%1,%2,%3}, {%4,%5,%6,%7}, {%8,%9}, {%0,%1,%2,%3};"
        : "+f"(c[0]), "+f"(c[1]), "+f"(c[2]), "+f"(c[3])
        : "r"(a[0]), "r"(a[1]), "r"(a[2]), "r"(a[3]), "r"(u0), "r"(u1));
}

__global__ void __launch_bounds__(256, 2)
fused_spiral(const float* x,
             const int* idx,            // int32 (JAX x64 disabled)
             const float* W1,
             const float* b1,
             const float* W2,
             const float* b2,
             float* out)
{
    extern __shared__ unsigned sm[];
    unsigned* Pp   = sm + P_OFF;
    int*      offs = (int*)(sm + OFFS_OFF);

    const int tid = threadIdx.x;
    const int m0  = blockIdx.x * TILE_M;
    const int warp = tid >> 5, lane = tid & 31;
    const int wm = warp & 3;                 // m group: wm*32 (both phases)
    const int wn = warp >> 2;                // n group (ph1: wn*32, ph2: wn*64)
    const int lg = lane >> 2, lq = lane & 3;

    // ---- Gather row offsets; defensive clamp ----
    for (int i = tid; i < TILE_M * K_; i += 256) {
        int r = i / K_;
        int k = i - r * K_;
        int m = m0 + r;
        int b = m / V_;
        int v = m - b * V_;
        int id = idx[v * K_ + k];
        id = id < 0 ? 0 : (id >= V_ ? V_ - 1 : id);
        offs[i] = (b * V_ + id) * C_;
    }
    __syncthreads();   // offs visible to all loaders

    // ================= Phase 1: gather + GEMM1 (128x64, K=576), k-chunks of 32 =================
    float acc1[2][4][4];
    #pragma unroll
    for (int i = 0; i < 2; i++)
        #pragma unroll
        for (int j = 0; j < 4; j++)
            #pragma unroll
            for (int l = 0; l < 4; l++) acc1[i][j][l] = 0.f;

    const int arow = tid >> 1, ah = tid & 1;     // A loader: row, 16-float half of 32
    const int brow = tid >> 2, bq = tid & 3;     // B loader: out-row, 8-float quarter

    float4 pa[4], pb[2];
    {   // prologue: chunk 0 (g=0, h=0)
        const float4* sA = (const float4*)(x + offs[arow * K_] + ah * 16);
        #pragma unroll
        for (int j = 0; j < 4; j++) pa[j] = sA[j];
        const float4* sB = (const float4*)(W1 + brow * KIN1_ + bq * 8);
        pb[0] = sB[0]; pb[1] = sB[1];
    }

    for (int kc = 0; kc < NCH1; kc++) {
        unsigned* As = sm + ((kc & 1) ? AS1B_OFF : AS1A_OFF);
        unsigned* Bs = sm + ((kc & 1) ? BS1B_OFF : BS1A_OFF);
        {   // STS prefetched slab (tf32 at store)
            unsigned* dA = As + arow * S_ST + ah * 16;
            #pragma unroll
            for (int j = 0; j < 4; j++) *(uint4*)(dA + j * 4) = f2tf4(pa[j]);
            unsigned* dB = Bs + brow * S_ST + bq * 8;
            *(uint4*)(dB)     = f2tf4(pb[0]);
            *(uint4*)(dB + 4) = f2tf4(pb[1]);
        }
        if (kc + 1 < NCH1) {   // prefetch next chunk (lands during mma below)
            int g = (kc + 1) >> 1, h = (kc + 1) & 1;
            const float4* sA = (const float4*)(x + offs[arow * K_ + g] + h * 32 + ah * 16);
            #pragma unroll
            for (int j = 0; j < 4; j++) pa[j] = sA[j];
            const float4* sB = (const float4*)(W1 + brow * KIN1_ + (kc + 1) * 32 + bq * 8);
            pb[0] = sB[0]; pb[1] = sB[1];
        }
        __syncthreads();       // slab ready; also recycles other buffer safely

        #pragma unroll
        for (int kk = 0; kk < 32; kk += 8) {
            unsigned a[2][4];
            #pragma unroll
            for (int ms = 0; ms < 2; ms++) {
                const unsigned* p = As + (wm * 32 + ms * 16 + lg) * S_ST + kk + lq;
                a[ms][0] = p[0];
                a[ms][1] = p[8 * S_ST];
                a[ms][2] = p[4];
                a[ms][3] = p[8 * S_ST + 4];
            }
            #pragma unroll
            for (int ns = 0; ns < 4; ns++) {
                const unsigned* p = Bs + (wn * 32 + ns * 8 + lg) * S_ST + kk + lq;
                unsigned u0 = p[0], u1 = p[4];
                mma8(acc1[0][ns], a[0], u0, u1);
                mma8(acc1[1][ns], a[1], u0, u1);
            }
        }
    }
    __syncthreads();   // all ph1 mma reads done before overlay region is rewritten

    // ---- P epilogue: + b1, tf32, into P region (stride 68) ----
    #pragma unroll
    for (int ms = 0; ms < 2; ms++) {
        #pragma unroll
        for (int ns = 0; ns < 4; ns++) {
            int row = wm * 32 + ms * 16 + lg;
            int col = wn * 32 + ns * 8 + lq * 2;
            float bv0 = b1[col], bv1 = b1[col + 1];
            *(uint2*)(Pp + row * P_ST + col) =
                make_uint2(f2tf(acc1[ms][ns][0] + bv0), f2tf(acc1[ms][ns][1] + bv1));
            *(uint2*)(Pp + (row + 8) * P_ST + col) =
                make_uint2(f2tf(acc1[ms][ns][2] + bv0), f2tf(acc1[ms][ns][3] + bv1));
        }
    }

    // ================= Phase 2: out = [P|xu](128x256) @ W2^T + b2 =================
    // r11 tiling: 4m x 2n warps, warp tile 32x64, two nc passes of 128 N.
    // A source: kc 0-1 from P smem; kc 2-7 streamed xu ring.
    const int wrow = tid >> 1, wh = tid & 1;   // W2 loader: out-row, 16-float half
    float4 pw[4], pxu[4];
    {   // prologue: W2 slab s=0
        const float4* sB = (const float4*)(W2 + (size_t)wrow * C_ + wh * 16);
        #pragma unroll
        for (int j = 0; j < 4; j++) pw[j] = sB[j];
    }

    int s = 0;
    #pragma unroll
    for (int nc = 0; nc < 2; nc++) {
        float acc2[2][8][4];
        #pragma unroll
        for (int i = 0; i < 2; i++)
            #pragma unroll
            for (int j = 0; j < 8; j++)
                #pragma unroll
                for (int l = 0; l < 4; l++) acc2[i][j][l] = 0.f;

        for (int kc = 0; kc < 8; kc++, s++) {
            unsigned* Bs = sm + ((s & 1) ? BS2B_OFF : BS2A_OFF);
            unsigned* Ax = sm + ((s & 1) ? AXB_OFF : AXA_OFF);
            {   // STS W2 slab
                unsigned* dB = Bs + wrow * S_ST + wh * 16;
                #pragma unroll
                for (int j = 0; j < 4; j++) *(uint4*)(dB + j * 4) = f2tf4(pw[j]);
            }
            if (kc >= 2) {   // STS xu slab (prefetched last iteration)
                unsigned* dA = Ax + arow * S_ST + ah * 16;
                #pragma unroll
                for (int j = 0; j < 4; j++) *(uint4*)(dA + j * 4) = f2tf4(pxu[j]);
            }
            if (s + 1 < 16) {   // prefetch next W2 slab (+ xu if needed)
                int nn = (s + 1) >> 3, kk2 = (s + 1) & 7;
                const float4* sB = (const float4*)(
                    W2 + (size_t)(nn * 128 + wrow) * C_ + kk2 * 32 + wh * 16);
                #pragma unroll
                for (int j = 0; j < 4; j++) pw[j] = sB[j];
                if (kk2 >= 2) {
                    const float4* sX = (const float4*)(
                        x + (size_t)(m0 + arow) * C_ + PC_ + (kk2 - 2) * 32 + ah * 16);
                    #pragma unroll
                    for (int j = 0; j < 4; j++) pxu[j] = sX[j];
                }
            }
            __syncthreads();   // slabs ready; first iter also covers P writes

            const unsigned* Abase = (kc < 2) ? (Pp + kc * 32) : Ax;
            const int ast = (kc < 2) ? P_ST : S_ST;

            #pragma unroll
            for (int kk = 0; kk < 32; kk += 8) {
                unsigned a[2][4];
                #pragma unroll
                for (int ms = 0; ms < 2; ms++) {
                    const unsigned* p = Abase + (wm * 32 + ms * 16 + lg) * ast + kk + lq;
                    a[ms][0] = p[0];
                    a[ms][1] = p[8 * ast];
                    a[ms][2] = p[4];
                    a[ms][3] = p[8 * ast + 4];
                }
                #pragma unroll
                for (int ns = 0; ns < 8; ns++) {
                    const unsigned* p = Bs + (wn * 64 + ns * 8 + lg) * S_ST + kk + lq;
                    unsigned u0 = p[0], u1 = p[4];
                    mma8(acc2[0][ns], a[0], u0, u1);
                    mma8(acc2[1][ns], a[1], u0, u1);
                }
            }
        }

        // epilogue: + b2 (global, cached), store out cols [nc*128, nc*128+128)
        #pragma unroll
        for (int ms = 0; ms < 2; ms++) {
            #pragma unroll
            for (int ns = 0; ns < 8; ns++) {
                int row = m0 + wm * 32 + ms * 16 + lg;
                int col = nc * 128 + wn * 64 + ns * 8 + lq * 2;
                float bv0 = b2[col], bv1 = b2[col + 1];
                *(float2*)(out + (size_t)row * C_ + col) =
                    make_float2(acc2[ms][ns][0] + bv0, acc2[ms][ns][1] + bv1);
                *(float2*)(out + (size_t)(row + 8) * C_ + col) =
                    make_float2(acc2[ms][ns][2] + bv0, acc2[ms][ns][3] + bv1);
            }
        }
    }
}

extern "C" void kernel_launch(void* const* d_in, const int* in_sizes, int n_in,
                              void* d_out, int out_size) {
    const float* x   = (const float*)d_in[0];
    const int*   idx = (const int*)d_in[1];
    const float* W1  = (const float*)d_in[2];
    const float* b1  = (const float*)d_in[3];
    const float* W2  = (const float*)d_in[4];
    const float* b2  = (const float*)d_in[5];
    float*       out = (float*)d_out;

    const int smem = SMEM_WORDS * 4;   // 108544 bytes -> 2 CTAs/SM
    cudaFuncSetAttribute(fused_spiral, cudaFuncAttributeMaxDynamicSharedMemorySize, smem);
    fused_spiral<<<M_TOTAL / TILE_M, 256, smem>>>(x, idx, W1, b1, W2, b2, out);
}